// round 6
// baseline (speedup 1.0000x reference)
#include <cuda_runtime.h>

// GCN fused kernel: per-sentence tile (64 rows), fp32, packed f32x2 FMA.
// Problem: BNK=1280, L=64, DIN=512, DOUT=256, NREL=40, M=81920.
//
// out[m,:] = relu( (P_in[head(m)] + b_in[lab]) * w_in + P_self[m] * w_self ) * mask
//   P_in   = rep @ W_in,  P_self = rep @ W_self
//   w_in   = sigmoid(g_in[head(m)] + b_gate_in[lab]) * adj_mask_in^2
//   w_self = sigmoid(g_self[m]) * adj_mask_loop^2
// head(m) is within the same 64-row sentence block -> fully fused per CTA.

#define BNK_ 1280
#define L_ 64
#define DIN_ 512
#define DOUT_ 256
#define TK_ 32

typedef unsigned long long u64;

__device__ __forceinline__ u64 ffma2(u64 a, u64 b, u64 c) {
    u64 d;
    asm("fma.rn.f32x2 %0, %1, %2, %3;" : "=l"(d) : "l"(a), "l"(b), "l"(c));
    return d;
}
__device__ __forceinline__ u64 dup2(float x) {
    u64 d;
    asm("mov.b64 %0, {%1, %1};" : "=l"(d) : "f"(x));
    return d;
}
__device__ __forceinline__ u64 pack2(float lo, float hi) {
    u64 d;
    asm("mov.b64 %0, {%1, %2};" : "=l"(d) : "f"(lo), "f"(hi));
    return d;
}
__device__ __forceinline__ float2 asf2(u64 v) {
    union { u64 u; float2 f; } x;
    x.u = v;
    return x.f;
}

// SMEM layout (floats):
//   As   [64][TK]      : rep tile (row-major)             2048
//   Bs   [TK][256]     : W tile                           8192
//   Pin  [64][256]     : P_in tile                       16384
//   gin  [64], gsf[64] : gate accumulators                 128
#define SMEM_FLOATS (64 * TK_ + TK_ * 256 + 64 * 256 + 128)
#define SMEM_BYTES (SMEM_FLOATS * 4)

extern "C" __global__ void __launch_bounds__(256, 2)
gcn_fused(const float* __restrict__ rep,
          const float* __restrict__ adj_mask_in,
          const float* __restrict__ adj_mask_loop,
          const float* __restrict__ mask,
          const float* __restrict__ W_in,
          const float* __restrict__ b_in,
          const float* __restrict__ Wg_in,
          const float* __restrict__ bg_in,
          const float* __restrict__ W_self,
          const float* __restrict__ Wg_self,
          const int* __restrict__ arc,
          const int* __restrict__ lab,
          float* __restrict__ out)
{
    extern __shared__ float smf[];
    float* As  = smf;                    // [64][TK]
    float* Bs  = As + 64 * TK_;          // [TK][256]
    float* Pin = Bs + TK_ * 256;         // [64][256]
    float* gin = Pin + 64 * 256;         // [64]
    float* gsf = gin + 64;               // [64]

    const int tid = threadIdx.x;
    const int tx = tid & 15;             // column group owner
    const int ty = tid >> 4;             // row group owner
    const int r0 = ty * 4;               // 4 rows per thread
    const int c0 = tx * 4;               // cols c0 + 64*j, j=0..3
    const int m0 = blockIdx.x * L_;      // sentence base row

    // ---------------- gate pre-pass (also warms rep tile into L2/L1) --------
    {
        int row = tid >> 2;              // 0..63
        int part = tid & 3;              // quarter of K
        const float4* rp = reinterpret_cast<const float4*>(
            rep + (size_t)(m0 + row) * DIN_ + part * 128);
        const float4* gi = reinterpret_cast<const float4*>(Wg_in + part * 128);
        const float4* gs = reinterpret_cast<const float4*>(Wg_self + part * 128);
        float ai = 0.f, asf = 0.f;
#pragma unroll 8
        for (int q = 0; q < 32; q++) {
            float4 v = rp[q];
            float4 wi = gi[q];
            float4 ws = gs[q];
            ai  += v.x * wi.x + v.y * wi.y + v.z * wi.z + v.w * wi.w;
            asf += v.x * ws.x + v.y * ws.y + v.z * ws.z + v.w * ws.w;
        }
        // reduce across the 4 parts (lanes row*4+part are contiguous, aligned)
        ai  += __shfl_xor_sync(0xffffffffu, ai, 1);
        ai  += __shfl_xor_sync(0xffffffffu, ai, 2);
        asf += __shfl_xor_sync(0xffffffffu, asf, 1);
        asf += __shfl_xor_sync(0xffffffffu, asf, 2);
        if (part == 0) { gin[row] = ai; gsf[row] = asf; }
    }

    u64 acc[4][8];  // [row i][col pair: j*2+p] packed f32x2 accumulators

    // ---------------- two GEMM phases: P_in then P_self ---------------------
#pragma unroll 1
    for (int phase = 0; phase < 2; phase++) {
        const float* W = phase ? W_self : W_in;
#pragma unroll
        for (int i = 0; i < 4; i++)
#pragma unroll
            for (int p = 0; p < 8; p++) acc[i][p] = 0ull;

#pragma unroll 1
        for (int kt = 0; kt < DIN_; kt += TK_) {
            __syncthreads();  // previous chunk's compute done (or gate pass)
            // load As: 64 x TK, row-major, 512 float4 total
#pragma unroll
            for (int t = 0; t < 2; t++) {
                int i = tid + 256 * t;
                int row = i >> 3, kk = i & 7;
                float4 v = *reinterpret_cast<const float4*>(
                    rep + (size_t)(m0 + row) * DIN_ + kt + kk * 4);
                *reinterpret_cast<float4*>(&As[row * TK_ + kk * 4]) = v;
            }
            // load Bs: TK x 256, 2048 float4 total
#pragma unroll
            for (int t = 0; t < 8; t++) {
                int i = tid + 256 * t;
                int kq = i >> 6, c4 = i & 63;
                float4 v = *reinterpret_cast<const float4*>(
                    W + (size_t)(kt + kq) * DOUT_ + c4 * 4);
                *reinterpret_cast<float4*>(&Bs[kq * DOUT_ + c4 * 4]) = v;
            }
            __syncthreads();

#pragma unroll 2
            for (int k = 0; k < TK_; k += 4) {
                float av[4][4];
#pragma unroll
                for (int i = 0; i < 4; i++) {
                    float4 a4 = *reinterpret_cast<const float4*>(&As[(r0 + i) * TK_ + k]);
                    av[i][0] = a4.x; av[i][1] = a4.y; av[i][2] = a4.z; av[i][3] = a4.w;
                }
#pragma unroll
                for (int kk = 0; kk < 4; kk++) {
                    u64 ad[4];
#pragma unroll
                    for (int i = 0; i < 4; i++) ad[i] = dup2(av[i][kk]);
#pragma unroll
                    for (int j = 0; j < 4; j++) {
                        float4 b = *reinterpret_cast<const float4*>(
                            &Bs[(k + kk) * DOUT_ + c0 + 64 * j]);
                        u64 b0 = pack2(b.x, b.y);
                        u64 b1 = pack2(b.z, b.w);
#pragma unroll
                        for (int i = 0; i < 4; i++) {
                            acc[i][j * 2]     = ffma2(ad[i], b0, acc[i][j * 2]);
                            acc[i][j * 2 + 1] = ffma2(ad[i], b1, acc[i][j * 2 + 1]);
                        }
                    }
                }
            }
        }

        if (phase == 0) {
            // stash P_in tile in SMEM (each thread writes only its own cells;
            // visibility guaranteed by the syncthreads at the start of phase 1)
#pragma unroll
            for (int i = 0; i < 4; i++)
#pragma unroll
                for (int j = 0; j < 4; j++) {
                    float2 lo = asf2(acc[i][j * 2]);
                    float2 hi = asf2(acc[i][j * 2 + 1]);
                    float4 v = make_float4(lo.x, lo.y, hi.x, hi.y);
                    *reinterpret_cast<float4*>(&Pin[(r0 + i) * DOUT_ + c0 + 64 * j]) = v;
                }
        }
    }

    __syncthreads();  // Pin + gates fully visible

    // ---------------- combine: gather + gates + relu + store ----------------
#pragma unroll
    for (int i = 0; i < 4; i++) {
        int r = r0 + i;
        int m = m0 + r;
        int lr = lab[m];
        int g = (arc[2 * m] * L_ + arc[2 * m + 1]) - m0;
        g &= 63;  // guaranteed in-range by construction; clamp for safety
        float min_ = adj_mask_in[m];
        float mlp_ = adj_mask_loop[m];
        float win = (1.f / (1.f + expf(-(gin[g] + bg_in[lr])))) * min_ * min_;
        float wsf = (1.f / (1.f + expf(-gsf[r]))) * mlp_ * mlp_;
        float mk = mask[m];
#pragma unroll
        for (int j = 0; j < 4; j++) {
            int c = c0 + 64 * j;
            float2 lo = asf2(acc[i][j * 2]);
            float2 hi = asf2(acc[i][j * 2 + 1]);
            float4 p = *reinterpret_cast<const float4*>(&Pin[g * DOUT_ + c]);
            float4 bb = *reinterpret_cast<const float4*>(&b_in[lr * DOUT_ + c]);
            float4 o;
            o.x = fmaxf((p.x + bb.x) * win + lo.x * wsf, 0.f) * mk;
            o.y = fmaxf((p.y + bb.y) * win + lo.y * wsf, 0.f) * mk;
            o.z = fmaxf((p.z + bb.z) * win + hi.x * wsf, 0.f) * mk;
            o.w = fmaxf((p.w + bb.w) * win + hi.y * wsf, 0.f) * mk;
            *reinterpret_cast<float4*>(&out[(size_t)m * DOUT_ + c]) = o;
        }
    }
}

extern "C" void kernel_launch(void* const* d_in, const int* in_sizes, int n_in,
                              void* d_out, int out_size)
{
    (void)in_sizes; (void)n_in; (void)out_size;
    cudaFuncSetAttribute(gcn_fused, cudaFuncAttributeMaxDynamicSharedMemorySize,
                         SMEM_BYTES);
    gcn_fused<<<BNK_, 256, SMEM_BYTES>>>(
        (const float*)d_in[0],   // rep
        (const float*)d_in[1],   // adj_mask_in
        (const float*)d_in[2],   // adj_mask_loop
        (const float*)d_in[3],   // mask
        (const float*)d_in[4],   // W_in
        (const float*)d_in[5],   // b_in
        (const float*)d_in[6],   // W_gate_in
        (const float*)d_in[7],   // b_gate_in
        (const float*)d_in[8],   // W_self
        (const float*)d_in[9],   // W_gate_self
        (const int*)d_in[10],    // adj_arc_in
        (const int*)d_in[11],    // adj_lab_in
        (float*)d_out);
}

// round 8
// speedup vs baseline: 2.7385x; 2.7385x over previous
#include <cuda_runtime.h>
#include <cstdint>

// GCN layer via mma.sync tf32 (HMMA) — tcgen05 unavailable on this toolchain
// (.target sm_103 without 'a' suffix).
// BNK=1280, L=64, DIN=512, DOUT=256, NREL=40.
// CTA = 128 rows (2 sentences), 256 threads, 8 warps (2M x 4N, warp 64x64).
// Phase 0: P_in = rep @ W_in  -> stash to SMEM (for within-CTA gather).
// Phase 1: P_self = rep @ W_self -> combine in registers with gathered P_in,
//          sigmoid gates (full fp32 GEMVs), relu, mask.

#define BNK_   1280
#define L_     64
#define DIN_   512
#define DOUT_  256
#define MTILE  128
#define KC     32
#define NCHUNK 16

typedef unsigned int u32;

// Pre-transposed, tf32-rounded, SW128-swizzled W: [which][chunk][n=256][k=32]
__device__ float WT_sw[2][NCHUNK][DOUT_][KC];

// ---- SMEM byte offsets ----
#define OFF_GIN 0
#define OFF_GSF 512
#define OFF_A0  1024
#define OFF_A1  (OFF_A0 + 16384)
#define OFF_B0  (OFF_A1 + 16384)
#define OFF_B1  (OFF_B0 + 32768)
#define OFF_PIN (OFF_B1 + 32768)
#define SMEM_TOTAL (OFF_PIN + 131072)   // 230400 B
// epilogue per-row params overlay the dead B0 stage buffer
#define OFF_WIN  OFF_B0
#define OFF_WSF  (OFF_B0 + 512)
#define OFF_MKV  (OFF_B0 + 1024)
#define OFF_GLI  (OFF_B0 + 1536)
#define OFF_LRI  (OFF_B0 + 2048)

__device__ __forceinline__ u32 smem_u32(const void* p) {
    u32 a;
    asm("{ .reg .u64 t; cvta.to.shared.u64 t, %1; cvt.u32.u64 %0, t; }"
        : "=r"(a) : "l"(p));
    return a;
}
__device__ __forceinline__ void cpa16(u32 dst, const void* src) {
    asm volatile("cp.async.cg.shared.global [%0], [%1], 16;\n"
                 :: "r"(dst), "l"(src));
}

#define MMA8(d, A, B0, B1)                                                    \
    asm volatile(                                                             \
        "mma.sync.aligned.m16n8k8.row.col.f32.tf32.tf32.f32 "                 \
        "{%0,%1,%2,%3}, {%4,%5,%6,%7}, {%8,%9}, {%0,%1,%2,%3};"               \
        : "+f"((d)[0]), "+f"((d)[1]), "+f"((d)[2]), "+f"((d)[3])              \
        : "r"(__float_as_uint((A)[0])), "r"(__float_as_uint((A)[1])),         \
          "r"(__float_as_uint((A)[2])), "r"(__float_as_uint((A)[3])),         \
          "r"(B0), "r"(B1))

#define LDMX4(x0, x1, x2, x3, addr)                                           \
    asm volatile(                                                             \
        "ldmatrix.sync.aligned.m8n8.x4.shared.b16 {%0,%1,%2,%3}, [%4];"       \
        : "=r"(x0), "=r"(x1), "=r"(x2), "=r"(x3) : "r"(addr))

#define CVT_TF32(dst, src)                                                    \
    asm("cvt.rna.tf32.f32 %0, %1;" : "=f"(dst) : "f"(__uint_as_float(src)))

// -------------------- prepass: transpose + tf32-round W ---------------------
extern "C" __global__ void prep_wt(const float* __restrict__ W_in,
                                   const float* __restrict__ W_self)
{
    int idx = blockIdx.x * 256 + threadIdx.x;   // 0 .. 262143
    int which = idx >> 17;
    int rem = idx & 131071;
    int k = rem >> 8;        // 0..511 (coalesced reads over n)
    int n = rem & 255;
    const float* W = which ? W_self : W_in;
    float v = W[k * DOUT_ + n];
    asm("cvt.rna.tf32.f32 %0, %1;" : "=f"(v) : "f"(v));
    int c = k >> 5, kk = k & 31;
    int byte = n * 128 + kk * 4;
    int sw = byte ^ ((byte >> 3) & 0x70);
    *(float*)((char*)&WT_sw[which][c][0][0] + sw) = v;
}

// ------------------------------- main kernel --------------------------------
extern "C" __global__ void __launch_bounds__(256, 1)
gcn_hmma(const float* __restrict__ rep,
         const float* __restrict__ adj_mask_in,
         const float* __restrict__ adj_mask_loop,
         const float* __restrict__ mask,
         const float* __restrict__ b_in,
         const float* __restrict__ bg_in,
         const float* __restrict__ Wg_in,
         const float* __restrict__ Wg_self,
         const int* __restrict__ arc,
         const int* __restrict__ lab,
         float* __restrict__ out)
{
    extern __shared__ char smem[];
    const u32 sb = smem_u32(smem);
    const int tid = threadIdx.x;
    const int ln = tid & 31;
    const int wid = tid >> 5;
    const int wm = wid >> 2;     // 0..1  (M half)
    const int wn = wid & 3;      // 0..3  (N quarter)
    const int g = ln >> 2;
    const int t = ln & 3;
    const int m0 = blockIdx.x * MTILE;

    // ldmatrix lane-address components
    const int rowA = wm * 64 + (ln & 7) + ((ln >> 3) & 1) * 8;   // + mt*16
    const int koffA = ((ln >> 4) & 1) * 16;
    const int rowB = wn * 64 + ((ln >> 4) & 1) * 8 + (ln & 7);   // + nt2*16
    const int koffB = ((ln >> 3) & 1) * 16;

    const u32 sA[2] = { sb + OFF_A0, sb + OFF_A1 };
    const u32 sB[2] = { sb + OFF_B0, sb + OFF_B1 };

    // precomputed cp.async A-destination (swizzled) offsets
    int arow[4], asw[4], aq[4];
#pragma unroll
    for (int i = 0; i < 4; i++) {
        int idx = tid + 256 * i;
        arow[i] = idx >> 3;
        aq[i] = idx & 7;
        int b = arow[i] * 128 + aq[i] * 16;
        asw[i] = b ^ ((b >> 3) & 0x70);
    }

#define LOAD_CHUNK(ch)                                                         \
    do {                                                                       \
        int p_ = (ch) >> 4, kc_ = (ch) & 15, s_ = (ch) & 1;                    \
        const char* ab = (const char*)rep + (size_t)m0 * 2048 + kc_ * 128;     \
        _Pragma("unroll")                                                      \
        for (int i = 0; i < 4; i++)                                            \
            cpa16(sA[s_] + asw[i], ab + (size_t)arow[i] * 2048 + aq[i] * 16);  \
        const char* bp = (const char*)WT_sw + (size_t)(p_ * 16 + kc_) * 32768; \
        _Pragma("unroll")                                                      \
        for (int i = 0; i < 8; i++) {                                          \
            int o = (tid + 256 * i) * 16;                                      \
            cpa16(sB[s_] + o, bp + o);                                         \
        }                                                                      \
        asm volatile("cp.async.commit_group;\n" ::: "memory");                 \
    } while (0)

    // prologue: chunks 0,1
    LOAD_CHUNK(0);
    LOAD_CHUNK(1);

    // ---------------- gate GEMVs (full fp32), overlap prologue --------------
    {
        int row = tid >> 1, half = tid & 1;
        const float4* rp = (const float4*)(rep + (size_t)(m0 + row) * DIN_ + half * 256);
        const float4* gi = (const float4*)(Wg_in + half * 256);
        const float4* gs = (const float4*)(Wg_self + half * 256);
        float ai = 0.f, as = 0.f;
#pragma unroll 8
        for (int q = 0; q < 64; q++) {
            float4 v = rp[q], wi = gi[q], ws = gs[q];
            ai += v.x * wi.x + v.y * wi.y + v.z * wi.z + v.w * wi.w;
            as += v.x * ws.x + v.y * ws.y + v.z * ws.z + v.w * ws.w;
        }
        ai += __shfl_xor_sync(0xffffffffu, ai, 1);
        as += __shfl_xor_sync(0xffffffffu, as, 1);
        if (!half) {
            ((float*)(smem + OFF_GIN))[row] = ai;
            ((float*)(smem + OFF_GSF))[row] = as;
        }
    }

    float acc[4][8][4];
#pragma unroll
    for (int mt = 0; mt < 4; mt++)
#pragma unroll
        for (int nt = 0; nt < 8; nt++)
#pragma unroll
            for (int q = 0; q < 4; q++) acc[mt][nt][q] = 0.f;

    // ------------------------------ main loop -------------------------------
    // 32 chunks: phase = c>>4 (0: W_in, 1: W_self), stage = c&1
#pragma unroll 2
    for (int c = 0; c < 32; c++) {
        const int s = c & 1;
        if (c == 31)
            asm volatile("cp.async.wait_group 0;" ::: "memory");
        else
            asm volatile("cp.async.wait_group 1;" ::: "memory");
        __syncthreads();

        const u32 aBase = sA[s], bBase = sB[s];
#pragma unroll
        for (int ks = 0; ks < 4; ks++) {
            float a[4][4];
#pragma unroll
            for (int mt = 0; mt < 4; mt++) {
                int byte = (rowA + mt * 16) * 128 + ks * 32 + koffA;
                byte ^= (byte >> 3) & 0x70;
                u32 x0, x1, x2, x3;
                LDMX4(x0, x1, x2, x3, aBase + byte);
                CVT_TF32(a[mt][0], x0);
                CVT_TF32(a[mt][1], x1);
                CVT_TF32(a[mt][2], x2);
                CVT_TF32(a[mt][3], x3);
            }
#pragma unroll
            for (int nt2 = 0; nt2 < 4; nt2++) {
                int byte = (rowB + nt2 * 16) * 128 + ks * 32 + koffB;
                byte ^= (byte >> 3) & 0x70;
                u32 b0, b1, b2, b3;
                LDMX4(b0, b1, b2, b3, bBase + byte);
#pragma unroll
                for (int mt = 0; mt < 4; mt++) {
                    MMA8(acc[mt][2 * nt2],     a[mt], b0, b1);
                    MMA8(acc[mt][2 * nt2 + 1], a[mt], b2, b3);
                }
            }
        }
        __syncthreads();  // all warps done with stage s before refill

        if (c < 30) LOAD_CHUNK(c + 2);

        if (c == 15) {
            // stash P_in tile to swizzled SMEM, zero accumulators
#pragma unroll
            for (int mt = 0; mt < 4; mt++)
#pragma unroll
                for (int nt = 0; nt < 8; nt++)
#pragma unroll
                    for (int h = 0; h < 2; h++) {
                        int r = wm * 64 + mt * 16 + g + h * 8;
                        int cc = (wn * 64 + nt * 8 + 2 * t) * 4;
                        u32 ad = sb + OFF_PIN + r * 1024 + (cc ^ ((r & 7) << 4));
                        asm volatile("st.shared.v2.f32 [%0], {%1,%2};"
                                     :: "r"(ad), "f"(acc[mt][nt][2 * h]),
                                        "f"(acc[mt][nt][2 * h + 1]) : "memory");
                    }
#pragma unroll
            for (int mt = 0; mt < 4; mt++)
#pragma unroll
                for (int nt = 0; nt < 8; nt++)
#pragma unroll
                    for (int q = 0; q < 4; q++) acc[mt][nt][q] = 0.f;
        }
    }

    // ---------------- epilogue: per-row params then combine ------------------
    if (tid < MTILE) {
        int r = tid, m = m0 + r;
        int lr = lab[m];
        int gl = (arc[2 * m] * L_ + arc[2 * m + 1]) - m0;
        gl &= (MTILE - 1);
        float mi = adj_mask_in[m], mlp = adj_mask_loop[m];
        float giv = ((float*)(smem + OFF_GIN))[gl] + bg_in[lr];
        float gsv = ((float*)(smem + OFF_GSF))[r];
        ((float*)(smem + OFF_WIN))[r] = (1.f / (1.f + expf(-giv))) * mi * mi;
        ((float*)(smem + OFF_WSF))[r] = (1.f / (1.f + expf(-gsv))) * mlp * mlp;
        ((float*)(smem + OFF_MKV))[r] = mask[m];
        ((int*)(smem + OFF_GLI))[r] = gl;
        ((int*)(smem + OFF_LRI))[r] = lr;
    }
    __syncthreads();

#pragma unroll
    for (int mt = 0; mt < 4; mt++)
#pragma unroll
        for (int h = 0; h < 2; h++) {
            int r = wm * 64 + mt * 16 + g + h * 8;
            float w_in = ((float*)(smem + OFF_WIN))[r];
            float w_sf = ((float*)(smem + OFF_WSF))[r];
            float mkr = ((float*)(smem + OFF_MKV))[r];
            int gl = ((int*)(smem + OFF_GLI))[r];
            int lr = ((int*)(smem + OFF_LRI))[r];
            const u32 pinrow = sb + OFF_PIN + gl * 1024;
            const int xr = (gl & 7) << 4;
            const float* bb = b_in + lr * DOUT_;
            float* op = out + (size_t)(m0 + r) * DOUT_;
#pragma unroll
            for (int nt = 0; nt < 8; nt++) {
                int cc = wn * 64 + nt * 8 + 2 * t;
                float px, py;
                asm volatile("ld.shared.v2.f32 {%0,%1}, [%2];"
                             : "=f"(px), "=f"(py)
                             : "r"(pinrow + ((cc * 4) ^ xr)));
                float2 bv = *(const float2*)(bb + cc);
                float2 o;
                o.x = fmaxf((px + bv.x) * w_in + acc[mt][nt][2 * h] * w_sf, 0.f) * mkr;
                o.y = fmaxf((py + bv.y) * w_in + acc[mt][nt][2 * h + 1] * w_sf, 0.f) * mkr;
                *(float2*)(op + cc) = o;
            }
        }
}

extern "C" void kernel_launch(void* const* d_in, const int* in_sizes, int n_in,
                              void* d_out, int out_size)
{
    (void)in_sizes; (void)n_in; (void)out_size;
    cudaFuncSetAttribute(gcn_hmma, cudaFuncAttributeMaxDynamicSharedMemorySize,
                         SMEM_TOTAL);
    prep_wt<<<1024, 256>>>((const float*)d_in[4], (const float*)d_in[8]);
    gcn_hmma<<<BNK_ / 2, 256, SMEM_TOTAL>>>(
        (const float*)d_in[0],   // rep
        (const float*)d_in[1],   // adj_mask_in
        (const float*)d_in[2],   // adj_mask_loop
        (const float*)d_in[3],   // mask
        (const float*)d_in[5],   // b_in
        (const float*)d_in[7],   // b_gate_in
        (const float*)d_in[6],   // W_gate_in
        (const float*)d_in[9],   // W_gate_self
        (const int*)d_in[10],    // adj_arc_in
        (const int*)d_in[11],    // adj_lab_in
        (float*)d_out);
}